// round 12
// baseline (speedup 1.0000x reference)
#include <cuda_runtime.h>
#include <cuda_fp16.h>
#include <math.h>
#include <stdint.h>

#define NN 2048
#define DD 128
#define FF 8
#define TM 64               // i-rows per CTA
#define TNJ 64              // j-cols per inner tile
#define JS 4                // j-split: CTAs per (f, i-tile)
#define JCOLS (NN / JS)     // 512 cols per CTA
#define NTILE (JCOLS / TNJ) // 8
#define THREADS 256
#define NCTAS ((NN / TM) * JS * FF)   // 1024

__device__ __half g_qh[FF * NN * DD];
__device__ __half g_dh[FF * NN * DD];
__device__ unsigned long long g_psim[FF * NN];
__device__ unsigned long long g_plab[FF * NN];
__device__ int    g_tdone[FF * (NN / TM)];
__device__ double g_loss;
__device__ int    g_count;
__device__ int    g_done;

__device__ __forceinline__ uint32_t smem_u32(const void* p) {
    uint32_t a;
    asm("{ .reg .u64 t; cvta.to.shared.u64 t, %1; cvt.u32.u64 %0, t; }" : "=r"(a) : "l"(p));
    return a;
}
__device__ __forceinline__ void cpa16(uint32_t dst, const void* src) {
    asm volatile("cp.async.cg.shared.global [%0], [%1], 16;" :: "r"(dst), "l"(src) : "memory");
}
#define CP_COMMIT() asm volatile("cp.async.commit_group;" ::: "memory")
#define CP_WAIT0()  asm volatile("cp.async.wait_group 0;" ::: "memory")

#define LDSM4(r, addr) \
    asm volatile("ldmatrix.sync.aligned.m8n8.x4.shared.b16 {%0,%1,%2,%3}, [%4];" \
                 : "=r"((r)[0]), "=r"((r)[1]), "=r"((r)[2]), "=r"((r)[3]) : "r"(addr))

__device__ __forceinline__ void mma_f16(float* c, const uint32_t* a, const uint32_t* b) {
    asm volatile(
        "mma.sync.aligned.m16n8k16.row.col.f32.f16.f16.f32 "
        "{%0,%1,%2,%3}, {%4,%5,%6,%7}, {%8,%9}, {%0,%1,%2,%3};"
        : "+f"(c[0]), "+f"(c[1]), "+f"(c[2]), "+f"(c[3])
        : "r"(a[0]), "r"(a[1]), "r"(a[2]), "r"(a[3]), "r"(b[0]), "r"(b[1]));
}

__device__ __forceinline__ uint32_t swz(int row, int chunk) {
    return (uint32_t)(row * 256 + ((chunk ^ (row & 7)) << 4));
}

// monotonic float->u32 map, then pack with inverted index (ties -> smaller j wins)
__device__ __forceinline__ unsigned long long packmax(float v, int j) {
    uint32_t b = __float_as_uint(v);
    b = (b & 0x80000000u) ? ~b : (b | 0x80000000u);
    return ((unsigned long long)b << 32) | (uint32_t)(2047 - j);
}

// SMEM: A 16K | B0 16K | B1 16K | diag 512B
#define SM_AH   0
#define SM_B0   16384
#define SM_BSTR 16384
#define SM_DIAG 49152
#define SM_TOTAL (49152 + 512)

// ---------------- prep: normalize -> fp16 + zero reduction state ----------------
__global__ void k_norm(const float* __restrict__ in0) {
    __shared__ float sd[DD * 9 + 9];
    int s = blockIdx.y, n = blockIdx.x;
    int tid = threadIdx.x;
    if (s == 0) {   // zero packed-argmax arrays + tile counters (every replay)
        int base = n * 8;
        if (tid < 8) g_psim[base + tid] = 0ULL;
        else if (tid < 16) g_plab[base + tid - 8] = 0ULL;
        else if (tid == 16 && n < FF * (NN / TM)) g_tdone[n] = 0;
        else if (tid == 17 && n == 0) { g_loss = 0.0; g_count = 0; g_done = 0; }
    }
    int f = tid >> 5, lane = tid & 31;
    const float4* base4 = (const float4*)(in0 + ((size_t)(s * NN + n)) * DD * FF);
    float4 v4 = base4[tid];
    {
        int e = tid * 4;
        sd[((e + 0) >> 3) * 9 + ((e + 0) & 7)] = v4.x;
        sd[((e + 1) >> 3) * 9 + ((e + 1) & 7)] = v4.y;
        sd[((e + 2) >> 3) * 9 + ((e + 2) & 7)] = v4.z;
        sd[((e + 3) >> 3) * 9 + ((e + 3) & 7)] = v4.w;
    }
    __syncthreads();
    float v[4], ssq = 0.f;
#pragma unroll
    for (int k = 0; k < 4; k++) {
        v[k] = sd[(lane + 32 * k) * 9 + f];
        ssq += v[k] * v[k];
    }
#pragma unroll
    for (int off = 16; off; off >>= 1) ssq += __shfl_xor_sync(0xffffffffu, ssq, off);
    float rn = 1.0f / sqrtf(ssq);
    __half* oh = (s == 0 ? g_qh : g_dh) + ((size_t)(f * NN + n)) * DD;
#pragma unroll
    for (int k = 0; k < 4; k++)
        oh[lane + 32 * k] = __float2half_rn(v[k] * rn);
}

// fp16 tile: 64 rows x 128 cols, swizzled
__device__ __forceinline__ void load_tile_async(uint32_t smbase, const __half* src, int tid) {
#pragma unroll
    for (int it = 0; it < (64 * 16) / THREADS; it++) {
        int idx = tid + it * THREADS;
        int row = idx >> 4, c = idx & 15;
        cpa16(smbase + swz(row, c), src + row * DD + c * 8);
    }
}

// ---------------- main ----------------
__global__ void __launch_bounds__(THREADS, 2) k_gemm(const float* __restrict__ label,
                                                     const float* __restrict__ pmargin,
                                                     float* __restrict__ gout, int nout) {
    extern __shared__ __align__(1024) char sm[];
    const uint32_t smb = smem_u32(sm);
    const int tid = threadIdx.x;
    const int w = tid >> 5, lane = tid & 31;
    const int g = lane >> 2, t4 = lane & 3;
    const int rowgrp = w >> 2, colgrp = w & 3;     // 2 x 4 warp grid: 32 rows x 16 cols
    const int f = blockIdx.y;
    const int bi = blockIdx.x >> 2;                // i-tile
    const int jc = blockIdx.x & (JS - 1);          // j-chunk
    const int i0 = bi * TM;
    const int jbase = jc * JCOLS;
    const float margin = *pmargin;
    const size_t fb = (size_t)f * NN;
    float* sdS = (float*)(sm + SM_DIAG);
    float* sdL = sdS + TM;

    load_tile_async(smb + SM_AH, g_qh + (fb + i0) * DD, tid);
    load_tile_async(smb + SM_B0, g_dh + (fb + jbase) * DD, tid);
    CP_COMMIT();

    // fused diag: warp w -> rows w*8 .. w*8+7 (needed by every chunk CTA)
    {
        const int d = lane * 4;
#pragma unroll 1
        for (int r8 = 0; r8 < 8; r8++) {
            int row = w * 8 + r8;
            const __half* qh = g_qh + (fb + i0 + row) * DD;
            const __half* dh = g_dh + (fb + i0 + row) * DD;
            float s = 0.f;
#pragma unroll
            for (int u = 0; u < 4; u++)
                s += __half2float(qh[d + u]) * __half2float(dh[d + u]);
#pragma unroll
            for (int off = 16; off; off >>= 1) s += __shfl_xor_sync(0xffffffffu, s, off);
            if (lane == 0) {
                sdS[row] = s;
                sdL[row] = label[(fb + i0 + row) * NN + (i0 + row)];
            }
        }
    }

    CP_WAIT0();
    __syncthreads();

    int rloc[4];
    float dS[4], dL[4];
    uint32_t loff[4];
#pragma unroll
    for (int mt = 0; mt < 2; mt++)
#pragma unroll
        for (int h = 0; h < 2; h++) {
            int k = mt * 2 + h;
            rloc[k] = rowgrp * 32 + mt * 16 + g + h * 8;
            dS[k] = sdS[rloc[k]];
            dL[k] = sdL[rloc[k]];
            loff[k] = (uint32_t)(((fb + i0 + rloc[k]) * NN) * 4);
        }

    float smax[4], lmax[4];
    int sidx[4], lidx[4];
#pragma unroll
    for (int k = 0; k < 4; k++) {
        smax[k] = -INFINITY; lmax[k] = -INFINITY; sidx[k] = 0; lidx[k] = 0;
    }
    float loss = 0.f;

    const int arow0 = rowgrp * 32 + (lane & 15);
    const int ahalf = lane >> 4;
    const int brow = colgrp * 16 + ((lane >> 4) & 1) * 8 + (lane & 7);
    const int bhalf = (lane >> 3) & 1;
    const int jl0 = colgrp * 16 + t4 * 2;
    const char* labc = (const char*)label;

#pragma unroll 1
    for (int t = 0; t < NTILE; t++) {
        if (t + 1 < NTILE) {
            uint32_t buf = (uint32_t)((t + 1) & 1);
            load_tile_async(smb + SM_B0 + buf * SM_BSTR,
                            g_dh + (fb + jbase + (size_t)(t + 1) * TNJ) * DD, tid);
            CP_COMMIT();
        }
        const uint32_t bb = smb + SM_B0 + (uint32_t)(t & 1) * SM_BSTR;
        const int j0 = jbase + t * TNJ;

        // label prefetch into registers (LDG latency hides under MMAs)
        float2 lab[2][4];   // [nt][k]
#pragma unroll
        for (int nt = 0; nt < 2; nt++)
#pragma unroll
            for (int k = 0; k < 4; k++)
                lab[nt][k] = *(const float2*)(labc + loff[k] + (uint32_t)(j0 + jl0 + nt * 8) * 4);

        float acc[2][2][4];
#pragma unroll
        for (int mt = 0; mt < 2; mt++)
#pragma unroll
            for (int nt = 0; nt < 2; nt++)
#pragma unroll
                for (int u = 0; u < 4; u++) acc[mt][nt][u] = 0.f;

#pragma unroll
        for (int ks = 0; ks < 8; ks++) {
            uint32_t a0[4], a1[4], b[4];
            LDSM4(a0, smb + SM_AH + swz(arow0,      2 * ks + ahalf));
            LDSM4(a1, smb + SM_AH + swz(arow0 + 16, 2 * ks + ahalf));
            LDSM4(b, bb + swz(brow, 2 * ks + bhalf));
            mma_f16(acc[0][0], a0, b + 0);
            mma_f16(acc[1][0], a1, b + 0);
            mma_f16(acc[0][1], a0, b + 2);
            mma_f16(acc[1][1], a1, b + 2);
        }

        // epilogue (diag contributes exactly `margin`; corrected at finalize)
#pragma unroll
        for (int mt = 0; mt < 2; mt++)
#pragma unroll
            for (int nt = 0; nt < 2; nt++) {
                const int j = j0 + jl0 + nt * 8;
#pragma unroll
                for (int h = 0; h < 2; h++) {
                    const int k = mt * 2 + h;
                    float2 l2 = lab[nt][k];
                    float s0 = acc[mt][nt][2 * h + 0];
                    float s1 = acc[mt][nt][2 * h + 1];
                    if (s0 > smax[k]) { smax[k] = s0; sidx[k] = j; }
                    if (s1 > smax[k]) { smax[k] = s1; sidx[k] = j + 1; }
                    if (l2.x > lmax[k]) { lmax[k] = l2.x; lidx[k] = j; }
                    if (l2.y > lmax[k]) { lmax[k] = l2.y; lidx[k] = j + 1; }
                    loss += fmaxf(margin - (dS[k] - s0) * (dL[k] - l2.x), 0.f);
                    loss += fmaxf(margin - (dS[k] - s1) * (dL[k] - l2.y), 0.f);
                }
            }

        if (t + 1 < NTILE) {
            CP_WAIT0();
            __syncthreads();
        }
    }

    // ---- loss ----
#pragma unroll
    for (int off = 16; off; off >>= 1) loss += __shfl_xor_sync(0xffffffffu, loss, off);
    if (lane == 0) atomicAdd(&g_loss, (double)loss);

    // ---- argmax: quad reduce then cross-colgrp merge ----
#pragma unroll
    for (int k = 0; k < 4; k++) {
#pragma unroll
        for (int o = 1; o < 4; o <<= 1) {
            float v; int ix;
            v = __shfl_xor_sync(0xffffffffu, smax[k], o); ix = __shfl_xor_sync(0xffffffffu, sidx[k], o);
            if (v > smax[k] || (v == smax[k] && ix < sidx[k])) { smax[k] = v; sidx[k] = ix; }
            v = __shfl_xor_sync(0xffffffffu, lmax[k], o); ix = __shfl_xor_sync(0xffffffffu, lidx[k], o);
            if (v > lmax[k] || (v == lmax[k] && ix < lidx[k])) { lmax[k] = v; lidx[k] = ix; }
        }
    }

    __syncthreads();                    // A smem dead -> reuse for merge
    float* ms = (float*)sm;             // [4][64]
    int*   mi = (int*)(sm + 1024);
    float* Ls = (float*)(sm + 2048);
    int*   Li = (int*)(sm + 3072);
    int*   gflag = (int*)(sm + 4096);
    if (t4 == 0) {
#pragma unroll
        for (int k = 0; k < 4; k++) {
            ms[colgrp * TM + rloc[k]] = smax[k];
            mi[colgrp * TM + rloc[k]] = sidx[k];
            Ls[colgrp * TM + rloc[k]] = lmax[k];
            Li[colgrp * TM + rloc[k]] = lidx[k];
        }
    }
    __syncthreads();
    if (tid < TM) {
        float bs = -INFINITY, bl = -INFINITY;
        int bsi = 0, bli = 0;
#pragma unroll
        for (int c = 0; c < 4; c++) {
            float v = ms[c * TM + tid]; int ix = mi[c * TM + tid];
            if (v > bs || (v == bs && ix < bsi)) { bs = v; bsi = ix; }
            float u = Ls[c * TM + tid]; int jx = Li[c * TM + tid];
            if (u > bl || (u == bl && jx < bli)) { bl = u; bli = jx; }
        }
        // publish this chunk's per-row winners
        atomicMax(&g_psim[fb + i0 + tid], packmax(bs, bsi));
        atomicMax(&g_plab[fb + i0 + tid], packmax(bl, bli));
    }

    // ---- group ticket: 4th CTA of (f, bi) counts matches for these 64 rows ----
    __threadfence();
    __syncthreads();
    if (tid == 0)
        gflag[0] = (atomicAdd(&g_tdone[f * (NN / TM) + bi], 1) == JS - 1) ? 1 : 0;
    __syncthreads();
    if (gflag[0]) {
        int match = 0;
        if (tid < TM) {
            unsigned long long ps = atomicAdd(&g_psim[fb + i0 + tid], 0ULL);
            unsigned long long pl = atomicAdd(&g_plab[fb + i0 + tid], 0ULL);
            match = ((uint32_t)ps == (uint32_t)pl);
        }
        match = __reduce_add_sync(0xffffffffu, match);
        if (lane == 0 && w < (TM / 32) && match) atomicAdd(&g_count, match);
    }

    // ---- global ticket: last CTA writes output ----
    __threadfence();
    __syncthreads();
    if (tid == 0) {
        int old = atomicAdd(&g_done, 1);
        if (old == NCTAS - 1) {
            double L = atomicAdd(&g_loss, 0.0);
            int    C = atomicAdd(&g_count, 0);
            double corr = (double)(FF * NN) * (double)fmaxf(margin, 0.f);
            if (nout > 0) gout[0] = (float)(L - corr);
            if (nout > 1) gout[1] = (float)C;
        }
    }
}

extern "C" void kernel_launch(void* const* d_in, const int* in_sizes, int n_in,
                              void* d_out, int out_size) {
    const float* out_matrix = (const float*)d_in[0];
    const float* label      = (const float*)d_in[1];
    const float* margin     = (const float*)d_in[2];
    float* out = (float*)d_out;

    cudaFuncSetAttribute(k_gemm, cudaFuncAttributeMaxDynamicSharedMemorySize, SM_TOTAL);

    dim3 gn(NN, 2);
    k_norm<<<gn, 256>>>(out_matrix);
    dim3 gm((NN / TM) * JS, FF);
    k_gemm<<<gm, THREADS, SM_TOTAL>>>(label, margin, out, out_size);
}

// round 13
// speedup vs baseline: 1.1016x; 1.1016x over previous
#include <cuda_runtime.h>
#include <cuda_fp16.h>
#include <math.h>
#include <stdint.h>

#define NN 2048
#define DD 128
#define FF 8
#define TM 64               // i-rows per CTA
#define TNJ 64              // j-cols per inner tile
#define JS 4                // j-split: CTAs per (f, i-tile)
#define JCOLS (NN / JS)     // 512
#define NTILE (JCOLS / TNJ) // 8
#define THREADS 256
#define NCTAS ((NN / TM) * JS * FF)   // 1024

__device__ __half g_qh[FF * NN * DD];
__device__ __half g_dh[FF * NN * DD];
__device__ float  g_dS[FF * NN];
__device__ float  g_dL[FF * NN];
__device__ unsigned long long g_psim[FF * NN];
__device__ unsigned long long g_plab[FF * NN];
__device__ int    g_tdone[FF * (NN / TM)];
__device__ double g_loss;
__device__ int    g_count;
__device__ int    g_done;

__device__ __forceinline__ uint32_t smem_u32(const void* p) {
    uint32_t a;
    asm("{ .reg .u64 t; cvta.to.shared.u64 t, %1; cvt.u32.u64 %0, t; }" : "=r"(a) : "l"(p));
    return a;
}
__device__ __forceinline__ void cpa16(uint32_t dst, const void* src) {
    asm volatile("cp.async.cg.shared.global [%0], [%1], 16;" :: "r"(dst), "l"(src) : "memory");
}
#define CP_COMMIT() asm volatile("cp.async.commit_group;" ::: "memory")
#define CP_WAIT0()  asm volatile("cp.async.wait_group 0;" ::: "memory")

#define LDSM4(r, addr) \
    asm volatile("ldmatrix.sync.aligned.m8n8.x4.shared.b16 {%0,%1,%2,%3}, [%4];" \
                 : "=r"((r)[0]), "=r"((r)[1]), "=r"((r)[2]), "=r"((r)[3]) : "r"(addr))

__device__ __forceinline__ void mma_f16(float* c, const uint32_t* a, const uint32_t* b) {
    asm volatile(
        "mma.sync.aligned.m16n8k16.row.col.f32.f16.f16.f32 "
        "{%0,%1,%2,%3}, {%4,%5,%6,%7}, {%8,%9}, {%0,%1,%2,%3};"
        : "+f"(c[0]), "+f"(c[1]), "+f"(c[2]), "+f"(c[3])
        : "r"(a[0]), "r"(a[1]), "r"(a[2]), "r"(a[3]), "r"(b[0]), "r"(b[1]));
}

__device__ __forceinline__ uint32_t swz(int row, int chunk) {
    return (uint32_t)(row * 256 + ((chunk ^ (row & 7)) << 4));
}

// monotonic float->u32, pack with inverted index (ties -> smaller j wins)
__device__ __forceinline__ unsigned long long packmax(float v, int j) {
    uint32_t b = __float_as_uint(v);
    b = (b & 0x80000000u) ? ~b : (b | 0x80000000u);
    return ((unsigned long long)b << 32) | (uint32_t)(2047 - j);
}

// SMEM: A 16K | B0 16K | B1 16K  (merge arrays overlay A at the end)
#define SM_AH   0
#define SM_B0   16384
#define SM_BSTR 16384
#define SM_TOTAL 49152

// ---------------- prep: normalize both sides + diag + zero state ----------------
// one block per n, 512 threads: tid<256 -> s=0 (q), else s=1 (d)
__global__ void k_norm(const float* __restrict__ in0, const float* __restrict__ label) {
    __shared__ float sq[DD * 9 + 9];
    __shared__ float sd[DD * 9 + 9];
    const int n = blockIdx.x;
    const int tid = threadIdx.x;
    const int side = tid >> 8;          // 0 = q, 1 = d
    const int t = tid & 255;

    // zeroing of reduction state (distinct threads; full coverage over grid)
    {
        if (tid >= 480 && tid < 488) g_psim[n * 8 + (tid - 480)] = 0ULL;
        if (tid >= 488 && tid < 496) g_plab[n * 8 + (tid - 488)] = 0ULL;
        if (tid == 496 && n < FF * (NN / TM)) g_tdone[n] = 0;
        if (tid == 497 && n == 0) { g_loss = 0.0; g_count = 0; g_done = 0; }
    }

    {   // stage [D][F] slice to smem with pitch-9 (conflict-free strided reads)
        const float4* base4 = (const float4*)(in0 + ((size_t)(side * NN + n)) * DD * FF);
        float4 v4 = base4[t];
        float* dst = side ? sd : sq;
        int e = t * 4;
        dst[(e >> 3) * 9 + (e & 7)]             = v4.x;
        dst[((e + 1) >> 3) * 9 + ((e + 1) & 7)] = v4.y;
        dst[((e + 2) >> 3) * 9 + ((e + 2) & 7)] = v4.z;
        dst[((e + 3) >> 3) * 9 + ((e + 3) & 7)] = v4.w;
    }
    __syncthreads();

    const int w = tid >> 5;             // 16 warps: 0-7 q-side (f=w), 8-15 d-side (f=w-8)
    const int lane = tid & 31;
    const int f = w & 7;
    float* buf = (w < 8) ? sq : sd;

    float v[4], ssq = 0.f;
#pragma unroll
    for (int k = 0; k < 4; k++) {
        v[k] = buf[(lane + 32 * k) * 9 + f];
        ssq += v[k] * v[k];
    }
#pragma unroll
    for (int off = 16; off; off >>= 1) ssq += __shfl_xor_sync(0xffffffffu, ssq, off);
    float rn = 1.0f / sqrtf(ssq);
#pragma unroll
    for (int k = 0; k < 4; k++) v[k] *= rn;

    __half* oh = ((w < 8) ? g_qh : g_dh) + ((size_t)(f * NN + n)) * DD;
#pragma unroll
    for (int k = 0; k < 4; k++)
        oh[lane + 32 * k] = __float2half_rn(v[k]);

    // d-warps write normalized values back to sd; q-warps then dot against them
    if (w >= 8) {
#pragma unroll
        for (int k = 0; k < 4; k++)
            sd[(lane + 32 * k) * 9 + f] = v[k];
    }
    __syncthreads();
    if (w < 8) {
        float s = 0.f;
#pragma unroll
        for (int k = 0; k < 4; k++)
            s += v[k] * sd[(lane + 32 * k) * 9 + f];
#pragma unroll
        for (int off = 16; off; off >>= 1) s += __shfl_xor_sync(0xffffffffu, s, off);
        if (lane == 0) {
            g_dS[f * NN + n] = s;
            g_dL[f * NN + n] = label[(size_t)(f * NN + n) * NN + n];
        }
    }
}

// fp16 tile: 64 rows x 128 cols, swizzled
__device__ __forceinline__ void load_tile_async(uint32_t smbase, const __half* src, int tid) {
#pragma unroll
    for (int it = 0; it < (64 * 16) / THREADS; it++) {
        int idx = tid + it * THREADS;
        int row = idx >> 4, c = idx & 15;
        cpa16(smbase + swz(row, c), src + row * DD + c * 8);
    }
}

// ---------------- main ----------------
__global__ void __launch_bounds__(THREADS, 3) k_gemm(const float* __restrict__ label,
                                                     const float* __restrict__ pmargin,
                                                     float* __restrict__ gout, int nout) {
    extern __shared__ __align__(1024) char sm[];
    const uint32_t smb = smem_u32(sm);
    const int tid = threadIdx.x;
    const int w = tid >> 5, lane = tid & 31;
    const int g = lane >> 2, t4 = lane & 3;
    const int rowgrp = w >> 2, colgrp = w & 3;     // 2 x 4 warp grid: 32 rows x 16 cols
    const int f = blockIdx.y;
    const int bi = blockIdx.x >> 2;
    const int jc = blockIdx.x & (JS - 1);
    const int i0 = bi * TM;
    const int jbase = jc * JCOLS;
    const float margin = *pmargin;
    const size_t fb = (size_t)f * NN;

    load_tile_async(smb + SM_AH, g_qh + (fb + i0) * DD, tid);
    load_tile_async(smb + SM_B0, g_dh + (fb + jbase) * DD, tid);
    CP_COMMIT();

    // per-thread row state from precomputed diag (overlaps with cp.async wait)
    int rloc[4];
    float dS[4], dL[4];
    uint32_t loff[4];
#pragma unroll
    for (int mt = 0; mt < 2; mt++)
#pragma unroll
        for (int h = 0; h < 2; h++) {
            int k = mt * 2 + h;
            rloc[k] = rowgrp * 32 + mt * 16 + g + h * 8;
            dS[k] = g_dS[fb + i0 + rloc[k]];
            dL[k] = g_dL[fb + i0 + rloc[k]];
            loff[k] = (uint32_t)(((fb + i0 + rloc[k]) * NN) * 4);
        }

    float smax[4], lmax[4];
    int sidx[4], lidx[4];
#pragma unroll
    for (int k = 0; k < 4; k++) {
        smax[k] = -INFINITY; lmax[k] = -INFINITY; sidx[k] = 0; lidx[k] = 0;
    }
    float loss = 0.f;

    const int arow0 = rowgrp * 32 + (lane & 15);
    const int ahalf = lane >> 4;
    const int brow = colgrp * 16 + ((lane >> 4) & 1) * 8 + (lane & 7);
    const int bhalf = (lane >> 3) & 1;
    const int jl0 = colgrp * 16 + t4 * 2;
    const char* labc = (const char*)label;

    CP_WAIT0();
    __syncthreads();

#pragma unroll 1
    for (int t = 0; t < NTILE; t++) {
        if (t + 1 < NTILE) {
            uint32_t buf = (uint32_t)((t + 1) & 1);
            load_tile_async(smb + SM_B0 + buf * SM_BSTR,
                            g_dh + (fb + jbase + (size_t)(t + 1) * TNJ) * DD, tid);
            CP_COMMIT();
        }
        const uint32_t bb = smb + SM_B0 + (uint32_t)(t & 1) * SM_BSTR;
        const int j0 = jbase + t * TNJ;

        // label prefetch into registers (LDG latency hides under MMAs)
        float2 lab[2][4];
#pragma unroll
        for (int nt = 0; nt < 2; nt++)
#pragma unroll
            for (int k = 0; k < 4; k++)
                lab[nt][k] = *(const float2*)(labc + loff[k] + (uint32_t)(j0 + jl0 + nt * 8) * 4);

        float acc[2][2][4];
#pragma unroll
        for (int mt = 0; mt < 2; mt++)
#pragma unroll
            for (int nt = 0; nt < 2; nt++)
#pragma unroll
                for (int u = 0; u < 4; u++) acc[mt][nt][u] = 0.f;

#pragma unroll
        for (int ks = 0; ks < 8; ks++) {
            uint32_t a0[4], a1[4], b[4];
            LDSM4(a0, smb + SM_AH + swz(arow0,      2 * ks + ahalf));
            LDSM4(a1, smb + SM_AH + swz(arow0 + 16, 2 * ks + ahalf));
            LDSM4(b, bb + swz(brow, 2 * ks + bhalf));
            mma_f16(acc[0][0], a0, b + 0);
            mma_f16(acc[1][0], a1, b + 0);
            mma_f16(acc[0][1], a0, b + 2);
            mma_f16(acc[1][1], a1, b + 2);
        }

        // epilogue (diag contributes exactly `margin`; corrected at finalize)
#pragma unroll
        for (int mt = 0; mt < 2; mt++)
#pragma unroll
            for (int nt = 0; nt < 2; nt++) {
                const int j = j0 + jl0 + nt * 8;
#pragma unroll
                for (int h = 0; h < 2; h++) {
                    const int k = mt * 2 + h;
                    float2 l2 = lab[nt][k];
                    float s0 = acc[mt][nt][2 * h + 0];
                    float s1 = acc[mt][nt][2 * h + 1];
                    if (s0 > smax[k]) { smax[k] = s0; sidx[k] = j; }
                    if (s1 > smax[k]) { smax[k] = s1; sidx[k] = j + 1; }
                    if (l2.x > lmax[k]) { lmax[k] = l2.x; lidx[k] = j; }
                    if (l2.y > lmax[k]) { lmax[k] = l2.y; lidx[k] = j + 1; }
                    loss += fmaxf(margin - (dS[k] - s0) * (dL[k] - l2.x), 0.f);
                    loss += fmaxf(margin - (dS[k] - s1) * (dL[k] - l2.y), 0.f);
                }
            }

        if (t + 1 < NTILE) {
            CP_WAIT0();
            __syncthreads();
        }
    }

    // ---- loss ----
#pragma unroll
    for (int off = 16; off; off >>= 1) loss += __shfl_xor_sync(0xffffffffu, loss, off);
    if (lane == 0) atomicAdd(&g_loss, (double)loss);

    // ---- argmax: quad reduce then cross-colgrp merge ----
#pragma unroll
    for (int k = 0; k < 4; k++) {
#pragma unroll
        for (int o = 1; o < 4; o <<= 1) {
            float v; int ix;
            v = __shfl_xor_sync(0xffffffffu, smax[k], o); ix = __shfl_xor_sync(0xffffffffu, sidx[k], o);
            if (v > smax[k] || (v == smax[k] && ix < sidx[k])) { smax[k] = v; sidx[k] = ix; }
            v = __shfl_xor_sync(0xffffffffu, lmax[k], o); ix = __shfl_xor_sync(0xffffffffu, lidx[k], o);
            if (v > lmax[k] || (v == lmax[k] && ix < lidx[k])) { lmax[k] = v; lidx[k] = ix; }
        }
    }

    __syncthreads();                    // A smem dead -> reuse for merge
    float* ms = (float*)sm;             // [4][64]
    int*   mi = (int*)(sm + 1024);
    float* Ls = (float*)(sm + 2048);
    int*   Li = (int*)(sm + 3072);
    int*   gflag = (int*)(sm + 4096);
    if (t4 == 0) {
#pragma unroll
        for (int k = 0; k < 4; k++) {
            ms[colgrp * TM + rloc[k]] = smax[k];
            mi[colgrp * TM + rloc[k]] = sidx[k];
            Ls[colgrp * TM + rloc[k]] = lmax[k];
            Li[colgrp * TM + rloc[k]] = lidx[k];
        }
    }
    __syncthreads();
    if (tid < TM) {
        float bs = -INFINITY, bl = -INFINITY;
        int bsi = 0, bli = 0;
#pragma unroll
        for (int c = 0; c < 4; c++) {
            float v = ms[c * TM + tid]; int ix = mi[c * TM + tid];
            if (v > bs || (v == bs && ix < bsi)) { bs = v; bsi = ix; }
            float u = Ls[c * TM + tid]; int jx = Li[c * TM + tid];
            if (u > bl || (u == bl && jx < bli)) { bl = u; bli = jx; }
        }
        atomicMax(&g_psim[fb + i0 + tid], packmax(bs, bsi));
        atomicMax(&g_plab[fb + i0 + tid], packmax(bl, bli));
    }

    // ---- group ticket: last CTA of (f, bi) counts matches for these 64 rows ----
    __threadfence();
    __syncthreads();
    if (tid == 0)
        gflag[0] = (atomicAdd(&g_tdone[f * (NN / TM) + bi], 1) == JS - 1) ? 1 : 0;
    __syncthreads();
    if (gflag[0]) {
        int match = 0;
        if (tid < TM) {
            unsigned long long ps = atomicAdd(&g_psim[fb + i0 + tid], 0ULL);
            unsigned long long pl = atomicAdd(&g_plab[fb + i0 + tid], 0ULL);
            match = ((uint32_t)ps == (uint32_t)pl);
        }
        match = __reduce_add_sync(0xffffffffu, match);
        if (lane == 0 && w < (TM / 32) && match) atomicAdd(&g_count, match);
    }

    // ---- global ticket: last CTA writes output ----
    __threadfence();
    __syncthreads();
    if (tid == 0) {
        int old = atomicAdd(&g_done, 1);
        if (old == NCTAS - 1) {
            double L = atomicAdd(&g_loss, 0.0);
            int    C = atomicAdd(&g_count, 0);
            double corr = (double)(FF * NN) * (double)fmaxf(margin, 0.f);
            if (nout > 0) gout[0] = (float)(L - corr);
            if (nout > 1) gout[1] = (float)C;
        }
    }
}

extern "C" void kernel_launch(void* const* d_in, const int* in_sizes, int n_in,
                              void* d_out, int out_size) {
    const float* out_matrix = (const float*)d_in[0];
    const float* label      = (const float*)d_in[1];
    const float* margin     = (const float*)d_in[2];
    float* out = (float*)d_out;

    cudaFuncSetAttribute(k_gemm, cudaFuncAttributeMaxDynamicSharedMemorySize, SM_TOTAL);

    k_norm<<<NN, 512>>>(out_matrix, label);
    dim3 gm((NN / TM) * JS, FF);
    k_gemm<<<gm, THREADS, SM_TOTAL>>>(label, margin, out, out_size);
}

// round 17
// speedup vs baseline: 1.3609x; 1.2354x over previous
#include <cuda_runtime.h>
#include <cuda_fp16.h>
#include <math.h>
#include <stdint.h>

#define NN 2048
#define DD 128
#define FF 8
#define TM 64               // i-rows per CTA
#define TNJ 64              // j-cols per tile
#define NTILE (NN / TNJ)    // 32
#define THREADS 256
#define NCTAS ((NN / TM) * FF)   // 256
#define LP 68               // label smem pitch (floats)

__device__ __half g_qh[FF * NN * DD];
__device__ __half g_dh[FF * NN * DD];
__device__ double g_loss;
__device__ int    g_count;
__device__ int    g_done;

__device__ __forceinline__ uint32_t smem_u32(const void* p) {
    uint32_t a;
    asm("{ .reg .u64 t; cvta.to.shared.u64 t, %1; cvt.u32.u64 %0, t; }" : "=r"(a) : "l"(p));
    return a;
}
__device__ __forceinline__ void cpa16(uint32_t dst, const void* src) {
    asm volatile("cp.async.cg.shared.global [%0], [%1], 16;" :: "r"(dst), "l"(src) : "memory");
}
#define CP_COMMIT() asm volatile("cp.async.commit_group;" ::: "memory")
#define CP_WAIT0()  asm volatile("cp.async.wait_group 0;" ::: "memory")

#define LDSM4(r, addr) \
    asm volatile("ldmatrix.sync.aligned.m8n8.x4.shared.b16 {%0,%1,%2,%3}, [%4];" \
                 : "=r"((r)[0]), "=r"((r)[1]), "=r"((r)[2]), "=r"((r)[3]) : "r"(addr))

__device__ __forceinline__ void mma_f16(float* c, const uint32_t* a, const uint32_t* b) {
    asm volatile(
        "mma.sync.aligned.m16n8k16.row.col.f32.f16.f16.f32 "
        "{%0,%1,%2,%3}, {%4,%5,%6,%7}, {%8,%9}, {%0,%1,%2,%3};"
        : "+f"(c[0]), "+f"(c[1]), "+f"(c[2]), "+f"(c[3])
        : "r"(a[0]), "r"(a[1]), "r"(a[2]), "r"(a[3]), "r"(b[0]), "r"(b[1]));
}

__device__ __forceinline__ uint32_t swz(int row, int chunk) {
    return (uint32_t)(row * 256 + ((chunk ^ (row & 7)) << 4));
}

// SMEM: A 16K | B0 16K | B1 16K | L0 17K | L1 17K | L2 17K | diag 512B
#define SM_AH   0
#define SM_B0   16384
#define SM_BSTR 16384
#define SM_L0   49152
#define SM_LSTR 17408       // 64 * 68 * 4
#define SM_DIAG 101376
#define SM_TOTAL (101376 + 512)

// ---------------- prep: normalize -> fp16 ----------------
__global__ void k_norm(const float* __restrict__ in0) {
    __shared__ float sd[DD * 9 + 9];
    int s = blockIdx.y, n = blockIdx.x;
    int tid = threadIdx.x;
    if (s == 0 && n == 0 && tid == 0) { g_loss = 0.0; g_count = 0; g_done = 0; }
    int f = tid >> 5, lane = tid & 31;
    const float4* base = (const float4*)(in0 + ((size_t)(s * NN + n)) * DD * FF);
    float4 v4 = base[tid];
    {
        int e = tid * 4;
        sd[((e + 0) >> 3) * 9 + ((e + 0) & 7)] = v4.x;
        sd[((e + 1) >> 3) * 9 + ((e + 1) & 7)] = v4.y;
        sd[((e + 2) >> 3) * 9 + ((e + 2) & 7)] = v4.z;
        sd[((e + 3) >> 3) * 9 + ((e + 3) & 7)] = v4.w;
    }
    __syncthreads();
    float v[4], ssq = 0.f;
#pragma unroll
    for (int k = 0; k < 4; k++) {
        v[k] = sd[(lane + 32 * k) * 9 + f];
        ssq += v[k] * v[k];
    }
#pragma unroll
    for (int off = 16; off; off >>= 1) ssq += __shfl_xor_sync(0xffffffffu, ssq, off);
    float rn = 1.0f / sqrtf(ssq);
    __half* oh = (s == 0 ? g_qh : g_dh) + ((size_t)(f * NN + n)) * DD;
#pragma unroll
    for (int k = 0; k < 4; k++)
        oh[lane + 32 * k] = __float2half_rn(v[k] * rn);
}

// fp16 tile: 64 rows x 128 cols, swizzled
__device__ __forceinline__ void load_tile_async(uint32_t smbase, const __half* src, int tid) {
#pragma unroll
    for (int it = 0; it < (64 * 16) / THREADS; it++) {
        int idx = tid + it * THREADS;
        int row = idx >> 4, c = idx & 15;
        cpa16(smbase + swz(row, c), src + row * DD + c * 8);
    }
}
// label tile: 64 rows x 64 floats -> pitch LP
__device__ __forceinline__ void load_lab_async(uint32_t smbase, const float* src, int tid) {
#pragma unroll
    for (int it = 0; it < 4; it++) {
        int idx = tid + it * THREADS;
        int row = idx >> 4, c = idx & 15;
        cpa16(smbase + (uint32_t)(row * (LP * 4) + c * 16), src + (size_t)row * NN + c * 4);
    }
}

// ---------------- main ----------------
__global__ void __launch_bounds__(THREADS, 2) k_gemm(const float* __restrict__ label,
                                                     const float* __restrict__ pmargin,
                                                     float* __restrict__ gout, int nout) {
    extern __shared__ __align__(1024) char sm[];
    const uint32_t smb = smem_u32(sm);
    const int tid = threadIdx.x;
    const int w = tid >> 5, lane = tid & 31;
    const int g = lane >> 2, t4 = lane & 3;
    const int rowgrp = w >> 2, colgrp = w & 3;     // 2 x 4 warp grid: 32 rows x 16 cols
    const int f = blockIdx.y;
    const int i0 = blockIdx.x * TM;
    const float margin = *pmargin;
    const size_t fb = (size_t)f * NN;
    float* sdS = (float*)(sm + SM_DIAG);
    float* sdL = sdS + TM;

    load_tile_async(smb + SM_AH, g_qh + (fb + i0) * DD, tid);
    load_tile_async(smb + SM_B0, g_dh + fb * DD, tid);
    load_lab_async(smb + SM_L0, label + (fb + i0) * NN, tid);
    CP_COMMIT();

    // fused diag (overlaps the cp.async): warp w -> rows w*8 .. w*8+7
    {
        const int d = lane * 4;
#pragma unroll 1
        for (int r8 = 0; r8 < 8; r8++) {
            int row = w * 8 + r8;
            const __half* qh = g_qh + (fb + i0 + row) * DD;
            const __half* dh = g_dh + (fb + i0 + row) * DD;
            float s = 0.f;
#pragma unroll
            for (int u = 0; u < 4; u++)
                s += __half2float(qh[d + u]) * __half2float(dh[d + u]);
#pragma unroll
            for (int off = 16; off; off >>= 1) s += __shfl_xor_sync(0xffffffffu, s, off);
            if (lane == 0) {
                sdS[row] = s;
                sdL[row] = label[(fb + i0 + row) * NN + (i0 + row)];
            }
        }
    }

    CP_WAIT0();
    __syncthreads();

    int rloc[4];
    float dS[4], dL[4];
    uint32_t lro[4];      // label row byte offsets within a label buffer
#pragma unroll
    for (int mt = 0; mt < 2; mt++)
#pragma unroll
        for (int h = 0; h < 2; h++) {
            int k = mt * 2 + h;
            rloc[k] = rowgrp * 32 + mt * 16 + g + h * 8;
            dS[k] = sdS[rloc[k]];
            dL[k] = sdL[rloc[k]];
            lro[k] = (uint32_t)((rloc[k] * LP + colgrp * 16 + t4 * 2) * 4);
        }

    float smax[4], lmax[4];
    int sidx[4], lidx[4];
#pragma unroll
    for (int k = 0; k < 4; k++) {
        smax[k] = -INFINITY; lmax[k] = -INFINITY; sidx[k] = 0; lidx[k] = 0;
    }
    float loss0 = 0.f, loss1 = 0.f;

    const int arow0 = rowgrp * 32 + (lane & 15);
    const int ahalf = lane >> 4;
    const int brow = colgrp * 16 + ((lane >> 4) & 1) * 8 + (lane & 7);
    const int bhalf = (lane >> 3) & 1;
    const int jl0 = colgrp * 16 + t4 * 2;

    float accA[2][2][4], accB[2][2][4];
    // label 3-ring: epi of tile t-1 reads lb_prev; prefetch of tile t+1 writes lb_next;
    // rotate left each iteration: (prev, cur, next) <- (cur, next, prev).
    // Safety: the buffer written at iter t held tile t-2's labels, consumed in the
    // epilogue at iter t-1, which completed behind that iteration's __syncthreads.
    uint32_t lb_prev = SM_L0 + 2 * SM_LSTR;   // unused until t=1
    uint32_t lb_cur  = SM_L0;                 // tile 0 labels (preloaded)
    uint32_t lb_next = SM_L0 + SM_LSTR;

#define MMA_TILE(ACC, BOFF)                                                        \
    do {                                                                           \
        _Pragma("unroll")                                                          \
        for (int mt = 0; mt < 2; mt++)                                             \
            _Pragma("unroll")                                                      \
            for (int nt = 0; nt < 2; nt++)                                         \
                _Pragma("unroll")                                                  \
                for (int u = 0; u < 4; u++) ACC[mt][nt][u] = 0.f;                  \
        _Pragma("unroll")                                                          \
        for (int ks = 0; ks < 8; ks++) {                                           \
            uint32_t a0[4], a1[4], b[4];                                           \
            LDSM4(a0, smb + SM_AH + swz(arow0,      2 * ks + ahalf));              \
            LDSM4(a1, smb + SM_AH + swz(arow0 + 16, 2 * ks + ahalf));              \
            LDSM4(b, smb + (BOFF) + swz(brow, 2 * ks + bhalf));                    \
            mma_f16(ACC[0][0], a0, b + 0);                                         \
            mma_f16(ACC[1][0], a1, b + 0);                                         \
            mma_f16(ACC[0][1], a0, b + 2);                                         \
            mma_f16(ACC[1][1], a1, b + 2);                                         \
        }                                                                          \
    } while (0)

#define EPI_TILE(ACC, LOFF, J0)                                                    \
    do {                                                                           \
        _Pragma("unroll")                                                          \
        for (int mt = 0; mt < 2; mt++)                                             \
            _Pragma("unroll")                                                      \
            for (int nt = 0; nt < 2; nt++) {                                       \
                const int j = (J0) + jl0 + nt * 8;                                 \
                _Pragma("unroll")                                                  \
                for (int h = 0; h < 2; h++) {                                      \
                    const int k = mt * 2 + h;                                      \
                    float2 l2 = *(const float2*)(sm + (LOFF) + lro[k] + nt * 32);  \
                    float s0 = ACC[mt][nt][2 * h + 0];                             \
                    float s1 = ACC[mt][nt][2 * h + 1];                             \
                    if (s0 > smax[k]) { smax[k] = s0; sidx[k] = j; }               \
                    if (s1 > smax[k]) { smax[k] = s1; sidx[k] = j + 1; }           \
                    if (l2.x > lmax[k]) { lmax[k] = l2.x; lidx[k] = j; }           \
                    if (l2.y > lmax[k]) { lmax[k] = l2.y; lidx[k] = j + 1; }       \
                    loss0 += fmaxf(margin - (dS[k] - s0) * (dL[k] - l2.x), 0.f);   \
                    loss1 += fmaxf(margin - (dS[k] - s1) * (dL[k] - l2.y), 0.f);   \
                }                                                                  \
            }                                                                      \
    } while (0)

#define ROTATE_RING()                                                              \
    do { uint32_t _t = lb_prev; lb_prev = lb_cur; lb_cur = lb_next; lb_next = _t; } while (0)

#pragma unroll 1
    for (int tt = 0; tt < NTILE; tt += 2) {
        // ---- t = tt (even): MMA -> accA, epilogue of t-1 (accB) ----
        {
            const int t = tt;
            if (t + 1 < NTILE) {
                load_tile_async(smb + SM_B0 + (uint32_t)((t + 1) & 1) * SM_BSTR,
                                g_dh + (fb + (size_t)(t + 1) * TNJ) * DD, tid);
                load_lab_async(smb + lb_next,
                               label + (fb + i0) * NN + (size_t)(t + 1) * TNJ, tid);
                CP_COMMIT();
            }
            MMA_TILE(accA, SM_B0 + (uint32_t)(t & 1) * SM_BSTR);
            if (t > 0) EPI_TILE(accB, lb_prev, (t - 1) * TNJ);
            ROTATE_RING();
            if (t + 1 < NTILE) { CP_WAIT0(); __syncthreads(); }
        }
        // ---- t = tt+1 (odd): MMA -> accB, epilogue of t-1 (accA) ----
        {
            const int t = tt + 1;
            if (t + 1 < NTILE) {
                load_tile_async(smb + SM_B0 + (uint32_t)((t + 1) & 1) * SM_BSTR,
                                g_dh + (fb + (size_t)(t + 1) * TNJ) * DD, tid);
                load_lab_async(smb + lb_next,
                               label + (fb + i0) * NN + (size_t)(t + 1) * TNJ, tid);
                CP_COMMIT();
            }
            MMA_TILE(accB, SM_B0 + (uint32_t)(t & 1) * SM_BSTR);
            EPI_TILE(accA, lb_prev, (t - 1) * TNJ);
            ROTATE_RING();
            if (t + 1 < NTILE) { CP_WAIT0(); __syncthreads(); }
        }
    }
    // final epilogue: tile NTILE-1 is in accB (odd parity); after the last rotation
    // lb_prev holds its labels.
    EPI_TILE(accB, lb_prev, (NTILE - 1) * TNJ);

    float loss = loss0 + loss1;

    // ---- loss ----
#pragma unroll
    for (int off = 16; off; off >>= 1) loss += __shfl_xor_sync(0xffffffffu, loss, off);
    if (lane == 0) atomicAdd(&g_loss, (double)loss);

    // ---- argmax: quad reduce then cross-colgrp merge ----
#pragma unroll
    for (int k = 0; k < 4; k++) {
#pragma unroll
        for (int o = 1; o < 4; o <<= 1) {
            float v; int ix;
            v = __shfl_xor_sync(0xffffffffu, smax[k], o); ix = __shfl_xor_sync(0xffffffffu, sidx[k], o);
            if (v > smax[k] || (v == smax[k] && ix < sidx[k])) { smax[k] = v; sidx[k] = ix; }
            v = __shfl_xor_sync(0xffffffffu, lmax[k], o); ix = __shfl_xor_sync(0xffffffffu, lidx[k], o);
            if (v > lmax[k] || (v == lmax[k] && ix < lidx[k])) { lmax[k] = v; lidx[k] = ix; }
        }
    }

    __syncthreads();                    // A smem dead -> reuse for merge
    float* ms = (float*)sm;             // [4][64]
    int*   mi = (int*)(sm + 1024);
    float* Ls = (float*)(sm + 2048);
    int*   Li = (int*)(sm + 3072);
    if (t4 == 0) {
#pragma unroll
        for (int k = 0; k < 4; k++) {
            ms[colgrp * TM + rloc[k]] = smax[k];
            mi[colgrp * TM + rloc[k]] = sidx[k];
            Ls[colgrp * TM + rloc[k]] = lmax[k];
            Li[colgrp * TM + rloc[k]] = lidx[k];
        }
    }
    __syncthreads();
    int match = 0;
    if (tid < TM) {
        float bs = -INFINITY, bl = -INFINITY;
        int bsi = 0, bli = 0;
#pragma unroll
        for (int c = 0; c < 4; c++) {
            float v = ms[c * TM + tid]; int ix = mi[c * TM + tid];
            if (v > bs || (v == bs && ix < bsi)) { bs = v; bsi = ix; }
            float u = Ls[c * TM + tid]; int jx = Li[c * TM + tid];
            if (u > bl || (u == bl && jx < bli)) { bl = u; bli = jx; }
        }
        match = (bsi == bli);
    }
    match = __reduce_add_sync(0xffffffffu, match);
    if (lane == 0 && w < (TM / 32) && match) atomicAdd(&g_count, match);

    // ---- fused finalize ----
    __syncthreads();
    if (tid == 0) {
        __threadfence();
        int old = atomicAdd(&g_done, 1);
        if (old == NCTAS - 1) {
            double L = atomicAdd(&g_loss, 0.0);
            int    C = atomicAdd(&g_count, 0);
            double corr = (double)(FF * NN) * (double)fmaxf(margin, 0.f);
            if (nout > 0) gout[0] = (float)(L - corr);
            if (nout > 1) gout[1] = (float)C;
        }
    }
}

extern "C" void kernel_launch(void* const* d_in, const int* in_sizes, int n_in,
                              void* d_out, int out_size) {
    const float* out_matrix = (const float*)d_in[0];
    const float* label      = (const float*)d_in[1];
    const float* margin     = (const float*)d_in[2];
    float* out = (float*)d_out;

    cudaFuncSetAttribute(k_gemm, cudaFuncAttributeMaxDynamicSharedMemorySize, SM_TOTAL);

    dim3 gn(NN, 2);
    k_norm<<<gn, 256>>>(out_matrix);
    dim3 gm(NN / TM, FF);
    k_gemm<<<gm, THREADS, SM_TOTAL>>>(label, margin, out, out_size);
}